// round 2
// baseline (speedup 1.0000x reference)
#include <cuda_runtime.h>
#include <math.h>

#define S_LEN 2048
#define HID   2048
#define NH    16
#define NKV   8
#define HD    128
#define ATT_SCALE 0.08838834764831845f   // 1/sqrt(128)
#define QP    68                         // padded 64-row stride for transposed tiles

// ---------------- scratch (static device globals: allocation-free) ----------
__device__ float g_q[(size_t)S_LEN * HID];          // 16 MB  (s, h, d)
__device__ float g_k[(size_t)S_LEN * NKV * HD];     //  8 MB  (s, kh, d)
__device__ float g_v[(size_t)S_LEN * NKV * HD];     //  8 MB  (s, kh, d)
__device__ float g_att[(size_t)S_LEN * HID];        // 16 MB  (s, h, d)

// ---------------- SGEMM NT: C[M,N] = A[M,K] * B[N,K]^T (all fp32) ----------
__global__ __launch_bounds__(256) void sgemm_nt(const float* __restrict__ A,
                                                const float* __restrict__ B,
                                                float* __restrict__ C,
                                                int M, int N, int K) {
    __shared__ float As[16 * 132];
    __shared__ float Bs[16 * 132];
    const int tid = threadIdx.x;
    const int tx = tid & 15, ty = tid >> 4;
    const int m0 = blockIdx.y << 7, n0 = blockIdx.x << 7;
    const int row0 = ty << 3, col0 = tx << 3;

    float acc[8][8];
#pragma unroll
    for (int i = 0; i < 8; ++i)
#pragma unroll
        for (int j = 0; j < 8; ++j) acc[i][j] = 0.f;

    for (int k0 = 0; k0 < K; k0 += 16) {
#pragma unroll
        for (int l = 0; l < 2; ++l) {
            int i = tid + (l << 8);          // 0..511
            int r = i >> 2;                  // 0..127
            int kq = (i & 3) << 2;           // {0,4,8,12}
            float4 va = *(const float4*)(A + (size_t)(m0 + r) * K + k0 + kq);
            As[(kq + 0) * 132 + r] = va.x;
            As[(kq + 1) * 132 + r] = va.y;
            As[(kq + 2) * 132 + r] = va.z;
            As[(kq + 3) * 132 + r] = va.w;
            float4 vb = *(const float4*)(B + (size_t)(n0 + r) * K + k0 + kq);
            Bs[(kq + 0) * 132 + r] = vb.x;
            Bs[(kq + 1) * 132 + r] = vb.y;
            Bs[(kq + 2) * 132 + r] = vb.z;
            Bs[(kq + 3) * 132 + r] = vb.w;
        }
        __syncthreads();
#pragma unroll
        for (int k = 0; k < 16; ++k) {
            float a[8], b[8];
            *(float4*)&a[0] = *(const float4*)&As[k * 132 + row0];
            *(float4*)&a[4] = *(const float4*)&As[k * 132 + row0 + 4];
            *(float4*)&b[0] = *(const float4*)&Bs[k * 132 + col0];
            *(float4*)&b[4] = *(const float4*)&Bs[k * 132 + col0 + 4];
#pragma unroll
            for (int i = 0; i < 8; ++i)
#pragma unroll
                for (int j = 0; j < 8; ++j) acc[i][j] += a[i] * b[j];
        }
        __syncthreads();
    }
#pragma unroll
    for (int i = 0; i < 8; ++i) {
        float* cp = C + (size_t)(m0 + row0 + i) * N + n0 + col0;
        *(float4*)cp       = make_float4(acc[i][0], acc[i][1], acc[i][2], acc[i][3]);
        *(float4*)(cp + 4) = make_float4(acc[i][4], acc[i][5], acc[i][6], acc[i][7]);
    }
}

// ---------------- fused RMSNorm + RoPE (per (s, head)); emits k_new --------
__global__ __launch_bounds__(128) void norm_rope(const float* __restrict__ fcos,
                                                 const float* __restrict__ fsin,
                                                 const float* __restrict__ qw,
                                                 const float* __restrict__ kw,
                                                 float* __restrict__ out) {
    const int s = blockIdx.x;
    const int hh = blockIdx.y;       // 0..15 = q heads, 16..23 = k heads
    const int i = threadIdx.x;       // 0..127

    float* base;
    const float* w;
    if (hh < NH) { base = g_q + (size_t)s * HID + hh * HD; w = qw; }
    else         { base = g_k + (size_t)s * (NKV * HD) + (hh - NH) * HD; w = kw; }

    float x = base[i];
    float v = x * x;
#pragma unroll
    for (int off = 16; off > 0; off >>= 1) v += __shfl_xor_sync(0xffffffffu, v, off);
    __shared__ float ws[4];
    __shared__ float sv[128];
    if ((i & 31) == 0) ws[i >> 5] = v;
    __syncthreads();
    float tot = ws[0] + ws[1] + ws[2] + ws[3];
    float r = rsqrtf(tot * (1.0f / 128.0f) + 1e-6f);
    sv[i] = x * r * w[i];
    __syncthreads();

    const int f = i & 63;
    float c  = fcos[s * 64 + f];
    float sn = fsin[s * 64 + f];
    float o;
    if (i < 64) o = sv[i] * c - sv[i + 64] * sn;
    else        o = sv[i - 64] * sn + sv[i] * c;
    base[i] = o;

    if (hh >= NH && s == S_LEN - 1)
        out[(size_t)S_LEN * HID + (size_t)(hh - NH) * HD + i] = o;   // k_new
}

// ---------------- v_new copy (kernel node; keeps graph pure) ---------------
__global__ void copy_vnew(float* __restrict__ out) {
    int t = threadIdx.x;   // 1024 threads
    out[(size_t)S_LEN * HID + NKV * HD + t] = g_v[(size_t)(S_LEN - 1) * NKV * HD + t];
}

// ---------------- causal flash attention, fp32, BM=BN=64 ------------------
__global__ __launch_bounds__(256) void flash(float* __restrict__ Oa) {
    extern __shared__ float sm[];
    float* Qs = sm;                   // [128][QP]  d-major (transposed)
    float* Ks = Qs + 128 * QP;        // [128][QP]  d-major
    float* Vs = Ks + 128 * QP;        // [64][128]  row-major
    float* Ps = Vs + 64 * 128;        // [64][QP]   c-major (transposed)

    const int tid = threadIdx.x;
    const int tx = tid & 15, ty = tid >> 4;
    const int h  = blockIdx.y;
    const int qt = blockIdx.x;
    const int qb = qt << 6;
    const int kvh = h >> 1;           // GQA: repeat(k, 2, axis=2)

    const float* qptr = g_q + h * HD;
    const float* kptr = g_k + kvh * HD;
    const float* vptr = g_v + kvh * HD;

    // load Q tile (transposed to d-major)
    for (int i = tid; i < 2048; i += 256) {
        int r = i >> 5, d = (i & 31) << 2;
        float4 qv = *(const float4*)(qptr + (size_t)(qb + r) * HID + d);
        Qs[(d + 0) * QP + r] = qv.x;
        Qs[(d + 1) * QP + r] = qv.y;
        Qs[(d + 2) * QP + r] = qv.z;
        Qs[(d + 3) * QP + r] = qv.w;
    }

    const int r0 = ty << 2, c0 = tx << 2, d0 = tx << 3;
    float m_i[4] = {-1e30f, -1e30f, -1e30f, -1e30f};
    float l_i[4] = {0.f, 0.f, 0.f, 0.f};
    float o[4][8];
#pragma unroll
    for (int i = 0; i < 4; ++i)
#pragma unroll
        for (int j = 0; j < 8; ++j) o[i][j] = 0.f;

    for (int jt = 0; jt <= qt; ++jt) {
        __syncthreads();              // protect Ks/Vs/Ps from previous iteration
        const int jb = jt << 6;
        for (int i = tid; i < 2048; i += 256) {
            int r = i >> 5, d = (i & 31) << 2;
            float4 kv = *(const float4*)(kptr + (size_t)(jb + r) * (NKV * HD) + d);
            Ks[(d + 0) * QP + r] = kv.x;
            Ks[(d + 1) * QP + r] = kv.y;
            Ks[(d + 2) * QP + r] = kv.z;
            Ks[(d + 3) * QP + r] = kv.w;
            float4 vv = *(const float4*)(vptr + (size_t)(jb + r) * (NKV * HD) + d);
            *(float4*)(Vs + r * HD + d) = vv;
        }
        __syncthreads();

        // S tile: 4x4 per thread over d=0..127
        float acc[4][4];
#pragma unroll
        for (int i = 0; i < 4; ++i)
#pragma unroll
            for (int j = 0; j < 4; ++j) acc[i][j] = 0.f;

#pragma unroll 8
        for (int d = 0; d < HD; ++d) {
            float4 qv = *(const float4*)(Qs + d * QP + r0);
            float4 kv = *(const float4*)(Ks + d * QP + c0);
            acc[0][0] += qv.x * kv.x; acc[0][1] += qv.x * kv.y; acc[0][2] += qv.x * kv.z; acc[0][3] += qv.x * kv.w;
            acc[1][0] += qv.y * kv.x; acc[1][1] += qv.y * kv.y; acc[1][2] += qv.y * kv.z; acc[1][3] += qv.y * kv.w;
            acc[2][0] += qv.z * kv.x; acc[2][1] += qv.z * kv.y; acc[2][2] += qv.z * kv.z; acc[2][3] += qv.z * kv.w;
            acc[3][0] += qv.w * kv.x; acc[3][1] += qv.w * kv.y; acc[3][2] += qv.w * kv.z; acc[3][3] += qv.w * kv.w;
        }

        const bool diag = (jt == qt);
#pragma unroll
        for (int i = 0; i < 4; ++i) {
            float s0 = acc[i][0] * ATT_SCALE;
            float s1 = acc[i][1] * ATT_SCALE;
            float s2 = acc[i][2] * ATT_SCALE;
            float s3 = acc[i][3] * ATT_SCALE;
            if (diag) {
                int row = r0 + i;
                if (c0 + 0 > row) s0 = -1e30f;
                if (c0 + 1 > row) s1 = -1e30f;
                if (c0 + 2 > row) s2 = -1e30f;
                if (c0 + 3 > row) s3 = -1e30f;
            }
            float mx = fmaxf(fmaxf(s0, s1), fmaxf(s2, s3));
#pragma unroll
            for (int off = 8; off > 0; off >>= 1)
                mx = fmaxf(mx, __shfl_xor_sync(0xffffffffu, mx, off, 16));
            float mnew  = fmaxf(m_i[i], mx);
            float alpha = __expf(m_i[i] - mnew);
            m_i[i] = mnew;
            float p0 = __expf(s0 - mnew);
            float p1 = __expf(s1 - mnew);
            float p2 = __expf(s2 - mnew);
            float p3 = __expf(s3 - mnew);
            float sum = p0 + p1 + p2 + p3;
#pragma unroll
            for (int off = 8; off > 0; off >>= 1)
                sum += __shfl_xor_sync(0xffffffffu, sum, off, 16);
            l_i[i] = l_i[i] * alpha + sum;
#pragma unroll
            for (int j = 0; j < 8; ++j) o[i][j] *= alpha;
            Ps[(c0 + 0) * QP + r0 + i] = p0;
            Ps[(c0 + 1) * QP + r0 + i] = p1;
            Ps[(c0 + 2) * QP + r0 + i] = p2;
            Ps[(c0 + 3) * QP + r0 + i] = p3;
        }
        __syncthreads();

        // O += P @ V
#pragma unroll 4
        for (int c = 0; c < 64; ++c) {
            float4 pv = *(const float4*)(Ps + c * QP + r0);
            float4 v0 = *(const float4*)(Vs + c * HD + d0);
            float4 v1 = *(const float4*)(Vs + c * HD + d0 + 4);
            o[0][0] += pv.x * v0.x; o[0][1] += pv.x * v0.y; o[0][2] += pv.x * v0.z; o[0][3] += pv.x * v0.w;
            o[0][4] += pv.x * v1.x; o[0][5] += pv.x * v1.y; o[0][6] += pv.x * v1.z; o[0][7] += pv.x * v1.w;
            o[1][0] += pv.y * v0.x; o[1][1] += pv.y * v0.y; o[1][2] += pv.y * v0.z; o[1][3] += pv.y * v0.w;
            o[1][4] += pv.y * v1.x; o[1][5] += pv.y * v1.y; o[1][6] += pv.y * v1.z; o[1][7] += pv.y * v1.w;
            o[2][0] += pv.z * v0.x; o[2][1] += pv.z * v0.y; o[2][2] += pv.z * v0.z; o[2][3] += pv.z * v0.w;
            o[2][4] += pv.z * v1.x; o[2][5] += pv.z * v1.y; o[2][6] += pv.z * v1.z; o[2][7] += pv.z * v1.w;
            o[3][0] += pv.w * v0.x; o[3][1] += pv.w * v0.y; o[3][2] += pv.w * v0.z; o[3][3] += pv.w * v0.w;
            o[3][4] += pv.w * v1.x; o[3][5] += pv.w * v1.y; o[3][6] += pv.w * v1.z; o[3][7] += pv.w * v1.w;
        }
    }

#pragma unroll
    for (int i = 0; i < 4; ++i) {
        float inv = 1.0f / l_i[i];
        float* op = Oa + (size_t)(qb + r0 + i) * HID + h * HD + d0;
        *(float4*)op       = make_float4(o[i][0] * inv, o[i][1] * inv, o[i][2] * inv, o[i][3] * inv);
        *(float4*)(op + 4) = make_float4(o[i][4] * inv, o[i][5] * inv, o[i][6] * inv, o[i][7] * inv);
    }
}

// ---------------- launch ---------------------------------------------------
static const int FLASH_SMEM = (128 * QP + 128 * QP + 64 * 128 + 64 * QP) * (int)sizeof(float);

extern "C" void kernel_launch(void* const* d_in, const int* in_sizes, int n_in,
                              void* d_out, int out_size) {
    (void)in_sizes; (void)n_in; (void)out_size;
    const float* hs = (const float*)d_in[0];
    const float* fc = (const float*)d_in[1];
    const float* fs = (const float*)d_in[2];
    // d_in[3] atten_mask: exact causal mask, applied analytically in flash
    const float* Wq = (const float*)d_in[4];
    const float* Wk = (const float*)d_in[5];
    const float* Wv = (const float*)d_in[6];
    const float* Wo = (const float*)d_in[7];
    const float* qw = (const float*)d_in[8];
    const float* kw = (const float*)d_in[9];
    float* out = (float*)d_out;

    void *pq, *pk, *pv, *pa;
    cudaGetSymbolAddress(&pq, g_q);
    cudaGetSymbolAddress(&pk, g_k);
    cudaGetSymbolAddress(&pv, g_v);
    cudaGetSymbolAddress(&pa, g_att);
    float* q   = (float*)pq;
    float* k   = (float*)pk;
    float* v   = (float*)pv;
    float* att = (float*)pa;

    cudaFuncSetAttribute(flash, cudaFuncAttributeMaxDynamicSharedMemorySize, FLASH_SMEM);

    // QKV projections
    sgemm_nt<<<dim3(16, 16), 256>>>(hs, Wq, q, S_LEN, HID,      HID);
    sgemm_nt<<<dim3(8, 16),  256>>>(hs, Wk, k, S_LEN, NKV * HD, HID);
    sgemm_nt<<<dim3(8, 16),  256>>>(hs, Wv, v, S_LEN, NKV * HD, HID);

    // RMSNorm + RoPE on q and k; emits k_new for s = S-1
    norm_rope<<<dim3(S_LEN, NH + NKV), 128>>>(fc, fs, qw, kw, out);

    // v_new
    copy_vnew<<<1, 1024>>>(out);

    // causal flash attention
    flash<<<dim3(S_LEN / 64, NH), 256, FLASH_SMEM>>>(att);

    // output projection -> y
    sgemm_nt<<<dim3(16, 16), 256>>>(att, Wo, out, S_LEN, HID, HID);
}

// round 11
// speedup vs baseline: 2.8469x; 2.8469x over previous
#include <cuda_runtime.h>
#include <math.h>

#define S_LEN 2048
#define HID   2048
#define NH    16
#define NKV   8
#define HD    128
#define ATT_SCALE 0.08838834764831845f   // 1/sqrt(128)

typedef unsigned int u32;

// ---------------- scratch (static device globals: allocation-free) ----------
__device__ float g_q[(size_t)S_LEN * HID];          // 16 MB  (s, h, d)
__device__ float g_k[(size_t)S_LEN * NKV * HD];     //  8 MB  (s, kh, d)
__device__ float g_v[(size_t)S_LEN * NKV * HD];     //  8 MB  (s, kh, d)
__device__ float g_att[(size_t)S_LEN * HID];        // 16 MB  (s, h, d)

// ---------------- tf32 helpers ---------------------------------------------
__device__ __forceinline__ u32 f2tf32(float x) {
    u32 r;
    asm("cvt.rna.tf32.f32 %0, %1;" : "=r"(r) : "f"(x));
    return r;
}

__device__ __forceinline__ void mma_tf32(float* d, const u32* a, u32 b0, u32 b1) {
    asm volatile(
        "mma.sync.aligned.m16n8k8.row.col.f32.tf32.tf32.f32 "
        "{%0,%1,%2,%3}, {%4,%5,%6,%7}, {%8,%9}, {%0,%1,%2,%3};\n"
        : "+f"(d[0]), "+f"(d[1]), "+f"(d[2]), "+f"(d[3])
        : "r"(a[0]), "r"(a[1]), "r"(a[2]), "r"(a[3]), "r"(b0), "r"(b1));
}

// ---------------- tf32 GEMM NT: C[M,N] = A[M,K] * B[N,K]^T ------------------
// BM=128, BN=128, BK=16. 8 warps: warp_m = wid&3 (32 rows), warp_n = wid>>2 (64 cols).
// Smem row-major with stride 20 (fragment LDS conflict-free).
#define GAS 20
__global__ __launch_bounds__(256, 2) void gemm_tf32(const float* __restrict__ A,
                                                    const float* __restrict__ B,
                                                    float* __restrict__ C,
                                                    int M, int N, int K) {
    __shared__ u32 As[128 * GAS];
    __shared__ u32 Bs[128 * GAS];
    const int tid = threadIdx.x;
    const int lane = tid & 31, g = lane >> 2, tg = lane & 3;
    const int wid = tid >> 5;
    const int wm = (wid & 3) << 5, wn = (wid >> 2) << 6;
    const int m0 = blockIdx.y << 7, n0 = blockIdx.x << 7;

    const int lr = tid >> 2;          // 0..63 (rows lr and lr+64)
    const int lc = (tid & 3) << 2;    // 0,4,8,12

    const float* Ag = A + (size_t)(m0 + lr) * K + lc;
    const float* Bg = B + (size_t)(n0 + lr) * K + lc;

    float acc[2][8][4];
#pragma unroll
    for (int mi = 0; mi < 2; ++mi)
#pragma unroll
        for (int ni = 0; ni < 8; ++ni)
#pragma unroll
            for (int j = 0; j < 4; ++j) acc[mi][ni][j] = 0.f;

    float4 pa0 = *(const float4*)(Ag);
    float4 pa1 = *(const float4*)(Ag + (size_t)64 * K);
    float4 pb0 = *(const float4*)(Bg);
    float4 pb1 = *(const float4*)(Bg + (size_t)64 * K);

    for (int k0 = 0; k0 < K; k0 += 16) {
        {
            u32* ap = As + lr * GAS + lc;
            ap[0] = f2tf32(pa0.x); ap[1] = f2tf32(pa0.y); ap[2] = f2tf32(pa0.z); ap[3] = f2tf32(pa0.w);
            u32* ap2 = As + (lr + 64) * GAS + lc;
            ap2[0] = f2tf32(pa1.x); ap2[1] = f2tf32(pa1.y); ap2[2] = f2tf32(pa1.z); ap2[3] = f2tf32(pa1.w);
            u32* bp = Bs + lr * GAS + lc;
            bp[0] = f2tf32(pb0.x); bp[1] = f2tf32(pb0.y); bp[2] = f2tf32(pb0.z); bp[3] = f2tf32(pb0.w);
            u32* bp2 = Bs + (lr + 64) * GAS + lc;
            bp2[0] = f2tf32(pb1.x); bp2[1] = f2tf32(pb1.y); bp2[2] = f2tf32(pb1.z); bp2[3] = f2tf32(pb1.w);
        }
        __syncthreads();
        if (k0 + 16 < K) {
            pa0 = *(const float4*)(Ag + k0 + 16);
            pa1 = *(const float4*)(Ag + (size_t)64 * K + k0 + 16);
            pb0 = *(const float4*)(Bg + k0 + 16);
            pb1 = *(const float4*)(Bg + (size_t)64 * K + k0 + 16);
        }
#pragma unroll
        for (int ks = 0; ks < 2; ++ks) {
            const int kk = ks << 3;
            u32 af[2][4];
#pragma unroll
            for (int mi = 0; mi < 2; ++mi) {
                const int mm = wm + (mi << 4);
                af[mi][0] = As[(mm + g) * GAS + kk + tg];
                af[mi][1] = As[(mm + g + 8) * GAS + kk + tg];
                af[mi][2] = As[(mm + g) * GAS + kk + tg + 4];
                af[mi][3] = As[(mm + g + 8) * GAS + kk + tg + 4];
            }
#pragma unroll
            for (int ni = 0; ni < 8; ++ni) {
                const int nn = wn + (ni << 3);
                u32 b0 = Bs[(nn + g) * GAS + kk + tg];
                u32 b1 = Bs[(nn + g) * GAS + kk + tg + 4];
                mma_tf32(acc[0][ni], af[0], b0, b1);
                mma_tf32(acc[1][ni], af[1], b0, b1);
            }
        }
        __syncthreads();
    }
#pragma unroll
    for (int mi = 0; mi < 2; ++mi) {
        const int rl = m0 + wm + (mi << 4) + g;
        const int rh = rl + 8;
#pragma unroll
        for (int ni = 0; ni < 8; ++ni) {
            const int c = n0 + wn + (ni << 3) + (tg << 1);
            *(float2*)(C + (size_t)rl * N + c) = make_float2(acc[mi][ni][0], acc[mi][ni][1]);
            *(float2*)(C + (size_t)rh * N + c) = make_float2(acc[mi][ni][2], acc[mi][ni][3]);
        }
    }
}

// ---------------- fused RMSNorm + RoPE (per (s, head)); emits k_new --------
__global__ __launch_bounds__(128) void norm_rope(const float* __restrict__ fcos,
                                                 const float* __restrict__ fsin,
                                                 const float* __restrict__ qw,
                                                 const float* __restrict__ kw,
                                                 float* __restrict__ out) {
    const int s = blockIdx.x;
    const int hh = blockIdx.y;       // 0..15 = q heads, 16..23 = k heads
    const int i = threadIdx.x;       // 0..127

    float* base;
    const float* w;
    if (hh < NH) { base = g_q + (size_t)s * HID + hh * HD; w = qw; }
    else         { base = g_k + (size_t)s * (NKV * HD) + (hh - NH) * HD; w = kw; }

    float x = base[i];
    float v = x * x;
#pragma unroll
    for (int off = 16; off > 0; off >>= 1) v += __shfl_xor_sync(0xffffffffu, v, off);
    __shared__ float ws[4];
    __shared__ float sv[128];
    if ((i & 31) == 0) ws[i >> 5] = v;
    __syncthreads();
    float tot = ws[0] + ws[1] + ws[2] + ws[3];
    float r = rsqrtf(tot * (1.0f / 128.0f) + 1e-6f);
    sv[i] = x * r * w[i];
    __syncthreads();

    const int f = i & 63;
    float c  = fcos[s * 64 + f];
    float sn = fsin[s * 64 + f];
    float o;
    if (i < 64) o = sv[i] * c - sv[i + 64] * sn;
    else        o = sv[i - 64] * sn + sv[i] * c;
    base[i] = o;

    if (hh >= NH && s == S_LEN - 1)
        out[(size_t)S_LEN * HID + (size_t)(hh - NH) * HD + i] = o;   // k_new
}

// ---------------- v_new copy (kernel node; keeps graph pure) ---------------
__global__ void copy_vnew(float* __restrict__ out) {
    int t = threadIdx.x;   // 1024 threads
    out[(size_t)S_LEN * HID + NKV * HD + t] = g_v[(size_t)(S_LEN - 1) * NKV * HD + t];
}

// ---------------- causal flash attention, tf32 mma, BM=128, BN=64 ----------
// 8 warps; warp w owns q rows [qb + 16w, qb + 16w + 16), full N width.
// c-frag rows: r_lo = 16w + g, r_hi = r_lo + 8; cols: ns*8 + 2*tg (+1).
#define KVS 132
__global__ __launch_bounds__(256) void flash_mma(float* __restrict__ Oa) {
    extern __shared__ u32 smx[];
    u32* Ks = smx;                 // [64][132]  row-major (kv, d), tf32
    u32* Vs = Ks + 64 * KVS;       // [64][132]  row-major (kv, d), tf32
    u32* Ps = Vs + 64 * KVS;       // [64][132]  k-major  (kvcol, qrow 0..127), tf32

    const int tid = threadIdx.x;
    const int wid = tid >> 5, lane = tid & 31;
    const int g = lane >> 2, tg = lane & 3;
    const int h = blockIdx.y, qt = blockIdx.x;
    const int qb = qt << 7;
    const int kvh = h >> 1;                         // GQA repeat(k, 2)

    const float* kptr = g_k + kvh * HD;
    const float* vptr = g_v + kvh * HD;

    const int r_lo = (wid << 4) + g;                // block-local q row (0..127)
    const int row_lo = qb + r_lo, row_hi = row_lo + 8;

    // Q fragments: loaded once, kept in registers (tf32)
    const float* qlo = g_q + (size_t)row_lo * HID + h * HD;
    const float* qhi = qlo + (size_t)8 * HID;
    u32 qf[16][4];
#pragma unroll
    for (int ks = 0; ks < 16; ++ks) {
        const int d0 = ks << 3;
        qf[ks][0] = f2tf32(qlo[d0 + tg]);
        qf[ks][1] = f2tf32(qhi[d0 + tg]);
        qf[ks][2] = f2tf32(qlo[d0 + tg + 4]);
        qf[ks][3] = f2tf32(qhi[d0 + tg + 4]);
    }

    float oacc[16][4];
#pragma unroll
    for (int ns = 0; ns < 16; ++ns)
#pragma unroll
        for (int j = 0; j < 4; ++j) oacc[ns][j] = 0.f;
    float m_lo = -1e30f, m_hi = -1e30f, l_lo = 0.f, l_hi = 0.f;

    for (int jb = 0; jb < qb + 128; jb += 64) {
        __syncthreads();           // previous iteration's Ks/Vs readers done
        for (int i = tid; i < 2048; i += 256) {
            const int r = i >> 5, d = (i & 31) << 2;
            float4 kv = *(const float4*)(kptr + (size_t)(jb + r) * (NKV * HD) + d);
            *(uint4*)(Ks + r * KVS + d) =
                make_uint4(f2tf32(kv.x), f2tf32(kv.y), f2tf32(kv.z), f2tf32(kv.w));
            float4 vv = *(const float4*)(vptr + (size_t)(jb + r) * (NKV * HD) + d);
            *(uint4*)(Vs + r * KVS + d) =
                make_uint4(f2tf32(vv.x), f2tf32(vv.y), f2tf32(vv.z), f2tf32(vv.w));
        }
        __syncthreads();

        // ---- S = Q K^T (tile 16 x 64 per warp) ----
        float sacc[8][4];
#pragma unroll
        for (int ns = 0; ns < 8; ++ns)
#pragma unroll
            for (int j = 0; j < 4; ++j) sacc[ns][j] = 0.f;

#pragma unroll
        for (int ks = 0; ks < 16; ++ks) {
            const int d0 = ks << 3;
#pragma unroll
            for (int ns = 0; ns < 8; ++ns) {
                u32 b0 = Ks[((ns << 3) + g) * KVS + d0 + tg];
                u32 b1 = Ks[((ns << 3) + g) * KVS + d0 + tg + 4];
                mma_tf32(sacc[ns], qf[ks], b0, b1);
            }
        }

        // ---- scale + causal mask + row max ----
        float mx_lo = -1e30f, mx_hi = -1e30f;
#pragma unroll
        for (int ns = 0; ns < 8; ++ns) {
            const int c0 = jb + (ns << 3) + (tg << 1), c1 = c0 + 1;
            float s0 = sacc[ns][0] * ATT_SCALE; if (c0 > row_lo) s0 = -1e30f;
            float s1 = sacc[ns][1] * ATT_SCALE; if (c1 > row_lo) s1 = -1e30f;
            float s2 = sacc[ns][2] * ATT_SCALE; if (c0 > row_hi) s2 = -1e30f;
            float s3 = sacc[ns][3] * ATT_SCALE; if (c1 > row_hi) s3 = -1e30f;
            sacc[ns][0] = s0; sacc[ns][1] = s1; sacc[ns][2] = s2; sacc[ns][3] = s3;
            mx_lo = fmaxf(mx_lo, fmaxf(s0, s1));
            mx_hi = fmaxf(mx_hi, fmaxf(s2, s3));
        }
        mx_lo = fmaxf(mx_lo, __shfl_xor_sync(0xffffffffu, mx_lo, 1));
        mx_lo = fmaxf(mx_lo, __shfl_xor_sync(0xffffffffu, mx_lo, 2));
        mx_hi = fmaxf(mx_hi, __shfl_xor_sync(0xffffffffu, mx_hi, 1));
        mx_hi = fmaxf(mx_hi, __shfl_xor_sync(0xffffffffu, mx_hi, 2));

        const float mn_lo = fmaxf(m_lo, mx_lo), mn_hi = fmaxf(m_hi, mx_hi);
        const float al_lo = __expf(m_lo - mn_lo), al_hi = __expf(m_hi - mn_hi);
        m_lo = mn_lo; m_hi = mn_hi;

        // ---- exp, write P (tf32) to smem, row sums ----
        float su_lo = 0.f, su_hi = 0.f;
#pragma unroll
        for (int ns = 0; ns < 8; ++ns) {
            float p0 = __expf(sacc[ns][0] - mn_lo);
            float p1 = __expf(sacc[ns][1] - mn_lo);
            float p2 = __expf(sacc[ns][2] - mn_hi);
            float p3 = __expf(sacc[ns][3] - mn_hi);
            su_lo += p0 + p1;
            su_hi += p2 + p3;
            const int cc = (ns << 3) + (tg << 1);
            Ps[(cc    ) * KVS + r_lo    ] = f2tf32(p0);
            Ps[(cc + 1) * KVS + r_lo    ] = f2tf32(p1);
            Ps[(cc    ) * KVS + r_lo + 8] = f2tf32(p2);
            Ps[(cc + 1) * KVS + r_lo + 8] = f2tf32(p3);
        }
        su_lo += __shfl_xor_sync(0xffffffffu, su_lo, 1);
        su_lo += __shfl_xor_sync(0xffffffffu, su_lo, 2);
        su_hi += __shfl_xor_sync(0xffffffffu, su_hi, 1);
        su_hi += __shfl_xor_sync(0xffffffffu, su_hi, 2);
        l_lo = l_lo * al_lo + su_lo;
        l_hi = l_hi * al_hi + su_hi;

#pragma unroll
        for (int ns = 0; ns < 16; ++ns) {
            oacc[ns][0] *= al_lo; oacc[ns][1] *= al_lo;
            oacc[ns][2] *= al_hi; oacc[ns][3] *= al_hi;
        }
        __syncwarp();              // P stores visible to own warp's frag loads

        // ---- O += P V (tile 16 x 128 per warp) ----
#pragma unroll
        for (int ks = 0; ks < 8; ++ks) {
            const int k0 = ks << 3;
            u32 af[4];
            af[0] = Ps[(k0 + tg) * KVS + r_lo];
            af[1] = Ps[(k0 + tg) * KVS + r_lo + 8];
            af[2] = Ps[(k0 + tg + 4) * KVS + r_lo];
            af[3] = Ps[(k0 + tg + 4) * KVS + r_lo + 8];
#pragma unroll
            for (int ns = 0; ns < 16; ++ns) {
                u32 b0 = Vs[(k0 + tg) * KVS + (ns << 3) + g];
                u32 b1 = Vs[(k0 + tg + 4) * KVS + (ns << 3) + g];
                mma_tf32(oacc[ns], af, b0, b1);
            }
        }
        __syncwarp();              // Ps reads done before next iteration's writes
    }

    const float i_lo = 1.0f / l_lo, i_hi = 1.0f / l_hi;
#pragma unroll
    for (int ns = 0; ns < 16; ++ns) {
        const int col = h * HD + (ns << 3) + (tg << 1);
        *(float2*)(Oa + (size_t)row_lo * HID + col) =
            make_float2(oacc[ns][0] * i_lo, oacc[ns][1] * i_lo);
        *(float2*)(Oa + (size_t)row_hi * HID + col) =
            make_float2(oacc[ns][2] * i_hi, oacc[ns][3] * i_hi);
    }
}

// ---------------- launch ---------------------------------------------------
static const int FLASH_SMEM = 3 * 64 * KVS * (int)sizeof(u32);   // 101376 B

extern "C" void kernel_launch(void* const* d_in, const int* in_sizes, int n_in,
                              void* d_out, int out_size) {
    (void)in_sizes; (void)n_in; (void)out_size;
    const float* hs = (const float*)d_in[0];
    const float* fc = (const float*)d_in[1];
    const float* fs = (const float*)d_in[2];
    // d_in[3] atten_mask: exact causal mask, applied analytically in flash
    const float* Wq = (const float*)d_in[4];
    const float* Wk = (const float*)d_in[5];
    const float* Wv = (const float*)d_in[6];
    const float* Wo = (const float*)d_in[7];
    const float* qw = (const float*)d_in[8];
    const float* kw = (const float*)d_in[9];
    float* out = (float*)d_out;

    void *pq, *pk, *pv, *pa;
    cudaGetSymbolAddress(&pq, g_q);
    cudaGetSymbolAddress(&pk, g_k);
    cudaGetSymbolAddress(&pv, g_v);
    cudaGetSymbolAddress(&pa, g_att);
    float* q   = (float*)pq;
    float* k   = (float*)pk;
    float* v   = (float*)pv;
    float* att = (float*)pa;

    cudaFuncSetAttribute(flash_mma, cudaFuncAttributeMaxDynamicSharedMemorySize, FLASH_SMEM);

    // QKV projections (tf32 tensor core)
    gemm_tf32<<<dim3(16, 16), 256>>>(hs, Wq, q, S_LEN, HID,      HID);
    gemm_tf32<<<dim3(8, 16),  256>>>(hs, Wk, k, S_LEN, NKV * HD, HID);
    gemm_tf32<<<dim3(8, 16),  256>>>(hs, Wv, v, S_LEN, NKV * HD, HID);

    // RMSNorm + RoPE on q and k; emits k_new for s = S-1
    norm_rope<<<dim3(S_LEN, NH + NKV), 128>>>(fc, fs, qw, kw, out);

    // v_new
    copy_vnew<<<1, 1024>>>(out);

    // causal flash attention (tf32 tensor core)
    flash_mma<<<dim3(S_LEN / 128, NH), 256, FLASH_SMEM>>>(att);

    // output projection -> y (tf32 tensor core)
    gemm_tf32<<<dim3(16, 16), 256>>>(att, Wo, out, S_LEN, HID, HID);
}